// round 2
// baseline (speedup 1.0000x reference)
#include <cuda_runtime.h>

#define B_  1024
#define S_  1024
#define E_  12
#define NQ  12
#define EPS_ 1e-5f
#define RPB 128   // rows per block in main kernel; 128 | S_ so blocks never cross a batch

// Per-sequence-position broadcast vectors (indexed by s, 0..1023)
__device__ float g_attn[S_ * E_];
__device__ float g_ffn [S_ * E_];

// ---------------------------------------------------------------------------
// Prep: one block per s (0..1023).
//   d_i(row r)  = cos(rx_i) * cos(x[r, i, 0])
//   attn[r][w]  = prod_{i<=w} d_i(r) (w>=1);  attn[r][0] = prod_{i>=1} d_i(r)
//   tok2[s,j]   = LN1(x[s,j,:] + attn[j,:])[0]     (corner attn rows j=0..11!)
//   z_j         = relu(cos(ry_j + tok2[s,j]))
//   ffn[s][e]   = b_ffn[e] + sum_j z_j * w_ffn[e,j]
// ---------------------------------------------------------------------------
__global__ void __launch_bounds__(32) prep_kernel(
    const float* __restrict__ x,
    const float* __restrict__ rx,
    const float* __restrict__ ry,
    const float* __restrict__ w_ffn,
    const float* __restrict__ b_ffn,
    const float* __restrict__ g1,
    const float* __restrict__ b1)
{
    const int s = blockIdx.x;
    const int t = threadIdx.x;

    __shared__ float xt[NQ * E_];        // x[s, 0:12, 0:12]
    __shared__ float corner[NQ * NQ];    // corner[j*12+i] = x[j, i, 0]
    __shared__ float crx[NQ];
    __shared__ float attn_c[NQ * NQ];    // attn rows for s'=0..11
    __shared__ float attn_own[NQ];       // attn row for this s
    __shared__ float z[NQ];

    const float* xs = x + (size_t)s * (S_ * E_);
    for (int k = t; k < NQ * E_; k += 32) xt[k] = xs[k];
    for (int k = t; k < NQ * NQ; k += 32) {
        const int j = k / NQ, i = k % NQ;
        corner[k] = x[(size_t)j * (S_ * E_) + i * E_];
    }
    if (t < NQ) crx[t] = cosf(rx[t]);
    __syncwarp();

    if (t < NQ) {
        // attn row for corner s' = t
        float d[NQ];
        #pragma unroll
        for (int i = 0; i < NQ; i++) d[i] = crx[i] * cosf(corner[t * NQ + i]);
        float p = 1.f;
        #pragma unroll
        for (int i = 0; i < NQ; i++) { p *= d[i]; if (i >= 1) attn_c[t * NQ + i] = p; }
        float q = 1.f;
        #pragma unroll
        for (int i = 1; i < NQ; i++) q *= d[i];
        attn_c[t * NQ + 0] = q;
    } else if (t == 12) {
        // attn row for this block's s
        float d[NQ];
        #pragma unroll
        for (int i = 0; i < NQ; i++) d[i] = crx[i] * cosf(xt[i * E_]);
        float p = 1.f;
        #pragma unroll
        for (int i = 0; i < NQ; i++) { p *= d[i]; if (i >= 1) attn_own[i] = p; }
        float q = 1.f;
        #pragma unroll
        for (int i = 1; i < NQ; i++) q *= d[i];
        attn_own[0] = q;
    }
    __syncwarp();

    if (t < NQ) {
        // tok2[s, t] = LN1(x[s,t,:] + attn_c[t,:])[0]
        float v[E_];
        float mu = 0.f;
        #pragma unroll
        for (int e = 0; e < E_; e++) { v[e] = xt[t * E_ + e] + attn_c[t * NQ + e]; mu += v[e]; }
        mu *= (1.f / E_);
        float var = 0.f;
        #pragma unroll
        for (int e = 0; e < E_; e++) { float dd = v[e] - mu; var += dd * dd; }
        var *= (1.f / E_);
        const float tok2 = (v[0] - mu) * rsqrtf(var + EPS_) * g1[0] + b1[0];
        z[t] = fmaxf(cosf(ry[t] + tok2), 0.f);
    }
    __syncwarp();

    if (t < E_) {
        float f = b_ffn[t];
        #pragma unroll
        for (int j = 0; j < NQ; j++) f += z[j] * w_ffn[t * NQ + j];
        g_ffn [s * E_ + t] = f;
        g_attn[s * E_ + t] = attn_own[t];
    }
}

// ---------------------------------------------------------------------------
// Main: out[b,s,:] = LN2( LN1(x[b,s,:] + attn[s,:]) + ffn[s,:] )
// Coalesced float4 streaming of x/attn/ffn tiles through padded (stride-13,
// conflict-free) shared memory; one thread per row of 12 elements.
// attn/ffn arrays are 48 KB each -> L2-resident, no extra HBM traffic.
// ---------------------------------------------------------------------------
__global__ void __launch_bounds__(RPB) main_kernel(
    const float* __restrict__ x,
    const float* __restrict__ g1, const float* __restrict__ b1,
    const float* __restrict__ g2, const float* __restrict__ b2,
    float* __restrict__ out)
{
    __shared__ float buf [RPB * 13];
    __shared__ float bufA[RPB * 13];
    __shared__ float bufF[RPB * 13];
    __shared__ float sg1[12], sb1[12], sg2[12], sb2[12];

    const int t = threadIdx.x;
    const size_t r0 = (size_t)blockIdx.x * RPB;           // global row
    const int s0 = (blockIdx.x & 7) * RPB;                // sequence offset (8 blocks/batch)

    if (t < 12) { sg1[t] = g1[t]; sb1[t] = b1[t]; sg2[t] = g2[t]; sb2[t] = b2[t]; }

    const float4* __restrict__ srcX = (const float4*)(x + r0 * 12);
    const float4* __restrict__ srcA = (const float4*)(g_attn + (size_t)s0 * 12);
    const float4* __restrict__ srcF = (const float4*)(g_ffn  + (size_t)s0 * 12);
    #pragma unroll
    for (int it = 0; it < 3; it++) {
        const int k = t + it * RPB;
        const int base = k * 4;
        const float4 vx = srcX[k];
        const float4 va = srcA[k];
        const float4 vf = srcF[k];
        const float ax[4] = {vx.x, vx.y, vx.z, vx.w};
        const float aa[4] = {va.x, va.y, va.z, va.w};
        const float af[4] = {vf.x, vf.y, vf.z, vf.w};
        #pragma unroll
        for (int c = 0; c < 4; c++) {
            const int idx = base + c;
            const int p = (idx / 12) * 13 + (idx % 12);
            buf [p] = ax[c];
            bufA[p] = aa[c];
            bufF[p] = af[c];
        }
    }
    __syncthreads();

    {
        float v[12];
        float* row = buf + t * 13;
        const float* ra = bufA + t * 13;
        const float* rf = bufF + t * 13;
        float mu = 0.f;
        #pragma unroll
        for (int e = 0; e < 12; e++) { v[e] = row[e] + ra[e]; mu += v[e]; }
        mu *= (1.f / 12.f);
        float var = 0.f;
        #pragma unroll
        for (int e = 0; e < 12; e++) { float dd = v[e] - mu; var += dd * dd; }
        var *= (1.f / 12.f);
        const float inv = rsqrtf(var + EPS_);

        float mu2 = 0.f;
        #pragma unroll
        for (int e = 0; e < 12; e++) {
            v[e] = (v[e] - mu) * inv * sg1[e] + sb1[e] + rf[e];
            mu2 += v[e];
        }
        mu2 *= (1.f / 12.f);
        float var2 = 0.f;
        #pragma unroll
        for (int e = 0; e < 12; e++) { float dd = v[e] - mu2; var2 += dd * dd; }
        var2 *= (1.f / 12.f);
        const float inv2 = rsqrtf(var2 + EPS_);

        #pragma unroll
        for (int e = 0; e < 12; e++)
            row[e] = (v[e] - mu2) * inv2 * sg2[e] + sb2[e];
    }
    __syncthreads();

    float4* __restrict__ dst = (float4*)(out + r0 * 12);
    #pragma unroll
    for (int it = 0; it < 3; it++) {
        const int k = t + it * RPB;
        const int base = k * 4;
        float4 vv;
        vv.x = buf[((base + 0) / 12) * 13 + ((base + 0) % 12)];
        vv.y = buf[((base + 1) / 12) * 13 + ((base + 1) % 12)];
        vv.z = buf[((base + 2) / 12) * 13 + ((base + 2) % 12)];
        vv.w = buf[((base + 3) / 12) * 13 + ((base + 3) % 12)];
        dst[k] = vv;
    }
}

extern "C" void kernel_launch(void* const* d_in, const int* in_sizes, int n_in,
                              void* d_out, int out_size)
{
    const float* x     = (const float*)d_in[0];
    const float* rx    = (const float*)d_in[1];
    const float* ry    = (const float*)d_in[2];
    const float* w_ffn = (const float*)d_in[3];
    const float* b_ffn = (const float*)d_in[4];
    const float* g1    = (const float*)d_in[5];
    const float* b1    = (const float*)d_in[6];
    const float* g2    = (const float*)d_in[7];
    const float* b2    = (const float*)d_in[8];
    float* out = (float*)d_out;

    prep_kernel<<<S_, 32>>>(x, rx, ry, w_ffn, b_ffn, g1, b1);
    main_kernel<<<(B_ * S_) / RPB, RPB>>>(x, g1, b1, g2, b2, out);
}

// round 3
// speedup vs baseline: 1.2381x; 1.2381x over previous
#include <cuda_runtime.h>

#define B_  1024
#define S_  1024
#define E_  12
#define NQ  12
#define EPS_ 1e-5f
#define NROWS (B_ * S_)

// Per-sequence-position broadcast vectors (indexed by s, 0..1023)
__device__ float g_attn[S_ * E_];
__device__ float g_ffn [S_ * E_];

// ---------------------------------------------------------------------------
// Prep: one block per s (0..1023). Computes g_attn[s,:], g_ffn[s,:].
//   d_i(row r)  = cos(rx_i) * cos(x[r, i, 0])
//   attn[r][w]  = prod_{i<=w} d_i(r) (w>=1);  attn[r][0] = prod_{i>=1} d_i(r)
//   tok2[s,j]   = LN1(x[s,j,:] + attn[j,:])[0]   (corner attn rows j=0..11)
//   z_j         = relu(cos(ry_j + tok2[s,j]))
//   ffn[s][e]   = b_ffn[e] + sum_j z_j * w_ffn[e,j]
// ---------------------------------------------------------------------------
__global__ void __launch_bounds__(32) prep_kernel(
    const float* __restrict__ x,
    const float* __restrict__ rx,
    const float* __restrict__ ry,
    const float* __restrict__ w_ffn,
    const float* __restrict__ b_ffn,
    const float* __restrict__ g1,
    const float* __restrict__ b1)
{
    const int s = blockIdx.x;
    const int t = threadIdx.x;

    __shared__ float xt[NQ * E_];        // x[s, 0:12, 0:12]
    __shared__ float corner[NQ * NQ];    // corner[j*12+i] = x[j, i, 0]
    __shared__ float crx[NQ];
    __shared__ float attn_c[NQ * NQ];    // attn rows for s'=0..11
    __shared__ float attn_own[NQ];       // attn row for this s
    __shared__ float z[NQ];

    const float* xs = x + (size_t)s * (S_ * E_);
    for (int k = t; k < NQ * E_; k += 32) xt[k] = xs[k];
    for (int k = t; k < NQ * NQ; k += 32) {
        const int j = k / NQ, i = k % NQ;
        corner[k] = x[(size_t)j * (S_ * E_) + i * E_];
    }
    if (t < NQ) crx[t] = cosf(rx[t]);
    __syncwarp();

    if (t < NQ) {
        float d[NQ];
        #pragma unroll
        for (int i = 0; i < NQ; i++) d[i] = crx[i] * cosf(corner[t * NQ + i]);
        float p = 1.f;
        #pragma unroll
        for (int i = 0; i < NQ; i++) { p *= d[i]; if (i >= 1) attn_c[t * NQ + i] = p; }
        float q = 1.f;
        #pragma unroll
        for (int i = 1; i < NQ; i++) q *= d[i];
        attn_c[t * NQ + 0] = q;
    } else if (t == 12) {
        float d[NQ];
        #pragma unroll
        for (int i = 0; i < NQ; i++) d[i] = crx[i] * cosf(xt[i * E_]);
        float p = 1.f;
        #pragma unroll
        for (int i = 0; i < NQ; i++) { p *= d[i]; if (i >= 1) attn_own[i] = p; }
        float q = 1.f;
        #pragma unroll
        for (int i = 1; i < NQ; i++) q *= d[i];
        attn_own[0] = q;
    }
    __syncwarp();

    if (t < NQ) {
        float v[E_];
        float mu = 0.f;
        #pragma unroll
        for (int e = 0; e < E_; e++) { v[e] = xt[t * E_ + e] + attn_c[t * NQ + e]; mu += v[e]; }
        mu *= (1.f / E_);
        float var = 0.f;
        #pragma unroll
        for (int e = 0; e < E_; e++) { float dd = v[e] - mu; var += dd * dd; }
        var *= (1.f / E_);
        const float tok2 = (v[0] - mu) * rsqrtf(var + EPS_) * g1[0] + b1[0];
        z[t] = fmaxf(cosf(ry[t] + tok2), 0.f);
    }
    __syncwarp();

    if (t < E_) {
        float f = b_ffn[t];
        #pragma unroll
        for (int j = 0; j < NQ; j++) f += z[j] * w_ffn[t * NQ + j];
        g_ffn [s * E_ + t] = f;
        g_attn[s * E_ + t] = attn_own[t];
    }
}

// ---------------------------------------------------------------------------
// Main: out[b,s,:] = LN2( LN1(x[b,s,:] + attn[s,:]) + ffn[s,:] )
// 3 lanes per row (one float4 chunk each), lanes 30-31 idle.
// All global accesses coalesced float4; LN reductions via 3-lane shuffles.
// No shared memory, no __syncthreads.
// ---------------------------------------------------------------------------
#define ACTIVE_MASK 0x3FFFFFFFu

__global__ void __launch_bounds__(128) main_kernel(
    const float* __restrict__ x,
    const float* __restrict__ g1, const float* __restrict__ b1,
    const float* __restrict__ g2, const float* __restrict__ b2,
    float* __restrict__ out)
{
    const int lane = threadIdx.x & 31;
    if (lane >= 30) return;

    const int warpId = (blockIdx.x * blockDim.x + threadIdx.x) >> 5; // global warp
    const int g = lane / 3;          // row within warp's 10 rows
    const int c = lane - g * 3;      // float4 chunk within row
    const int base = g * 3;          // first lane of this 3-lane group

    int row = warpId * 10 + g;
    const bool valid = (row < NROWS);
    if (!valid) row = NROWS - 1;     // clamp: stay convergent for shuffles
    const int s = row & (S_ - 1);

    const float4 vx = ((const float4*)x)[(size_t)row * 3 + c];
    const float4 va = ((const float4*)g_attn)[s * 3 + c];
    const float4 vf = ((const float4*)g_ffn )[s * 3 + c];
    const float4 w1g = ((const float4*)g1)[c];
    const float4 w1b = ((const float4*)b1)[c];
    const float4 w2g = ((const float4*)g2)[c];
    const float4 w2b = ((const float4*)b2)[c];

    float v0 = vx.x + va.x, v1 = vx.y + va.y, v2 = vx.z + va.z, v3 = vx.w + va.w;

    // --- LN1 stats via 3-lane reduction ---
    float ps = v0 + v1 + v2 + v3;
    float pq = v0 * v0 + v1 * v1 + v2 * v2 + v3 * v3;
    float sum = __shfl_sync(ACTIVE_MASK, ps, base)
              + __shfl_sync(ACTIVE_MASK, ps, base + 1)
              + __shfl_sync(ACTIVE_MASK, ps, base + 2);
    float sq  = __shfl_sync(ACTIVE_MASK, pq, base)
              + __shfl_sync(ACTIVE_MASK, pq, base + 1)
              + __shfl_sync(ACTIVE_MASK, pq, base + 2);
    float mu  = sum * (1.f / 12.f);
    float var = fmaxf(sq * (1.f / 12.f) - mu * mu, 0.f);
    float inv = rsqrtf(var + EPS_);

    v0 = (v0 - mu) * inv * w1g.x + w1b.x + vf.x;
    v1 = (v1 - mu) * inv * w1g.y + w1b.y + vf.y;
    v2 = (v2 - mu) * inv * w1g.z + w1b.z + vf.z;
    v3 = (v3 - mu) * inv * w1g.w + w1b.w + vf.w;

    // --- LN2 stats ---
    ps = v0 + v1 + v2 + v3;
    pq = v0 * v0 + v1 * v1 + v2 * v2 + v3 * v3;
    sum = __shfl_sync(ACTIVE_MASK, ps, base)
        + __shfl_sync(ACTIVE_MASK, ps, base + 1)
        + __shfl_sync(ACTIVE_MASK, ps, base + 2);
    sq  = __shfl_sync(ACTIVE_MASK, pq, base)
        + __shfl_sync(ACTIVE_MASK, pq, base + 1)
        + __shfl_sync(ACTIVE_MASK, pq, base + 2);
    mu  = sum * (1.f / 12.f);
    var = fmaxf(sq * (1.f / 12.f) - mu * mu, 0.f);
    inv = rsqrtf(var + EPS_);

    if (valid) {
        float4 o;
        o.x = (v0 - mu) * inv * w2g.x + w2b.x;
        o.y = (v1 - mu) * inv * w2g.y + w2b.y;
        o.z = (v2 - mu) * inv * w2g.z + w2b.z;
        o.w = (v3 - mu) * inv * w2g.w + w2b.w;
        ((float4*)out)[(size_t)row * 3 + c] = o;
    }
}

extern "C" void kernel_launch(void* const* d_in, const int* in_sizes, int n_in,
                              void* d_out, int out_size)
{
    const float* x     = (const float*)d_in[0];
    const float* rx    = (const float*)d_in[1];
    const float* ry    = (const float*)d_in[2];
    const float* w_ffn = (const float*)d_in[3];
    const float* b_ffn = (const float*)d_in[4];
    const float* g1    = (const float*)d_in[5];
    const float* b1    = (const float*)d_in[6];
    const float* g2    = (const float*)d_in[7];
    const float* b2    = (const float*)d_in[8];
    float* out = (float*)d_out;

    prep_kernel<<<S_, 32>>>(x, rx, ry, w_ffn, b_ffn, g1, b1);

    // 128 threads = 4 warps = 40 rows per block
    const int rows_per_block = 40;
    const int blocks = (NROWS + rows_per_block - 1) / rows_per_block;
    main_kernel<<<blocks, 128>>>(x, g1, b1, g2, b2, out);
}